// round 10
// baseline (speedup 1.0000x reference)
#include <cuda_runtime.h>
#include <cuda_fp16.h>
#include <cstdint>

// ============================================================================
// LinearCapsPro:  out[b,c] = sqrt( u_c^T (W_c W_c^T + eps I)^{-1} u_c ),
//                 u_c = W_c x_b
// Restructured:   G_c = R_c R_c^T (Cholesky)  =>  out[b,c] = || (R_c^{-1} W_c) x_b ||
// Prep W' = R^{-1} W (tiny), then ONE fp16 GEMM y = x @ W'^T with a fused
// sum-of-squares + sqrt epilogue (y never touches memory).
//
// R9 evidence: 8 warps/SM in any arrangement -> tensor pipe 48% busy; stall
// is the intra-warp LDS->MMA short-scoreboard at each block start. R10:
// software-pipeline fragments — per-stage A batch loaded once up front, B
// double-buffered in registers so each group's loads hide under the previous
// group's 32 MMAs. Config otherwise identical to R9 (128x128, 4w, 2 CTA/SM).
// ============================================================================

#define BATCH 8192
#define KDIM 512
#define NTOT 8192          // C*D
#define NUM_CAPS 1024
#define EPS_REG 1e-4f

#define BM 128
#define BN 128
#define BK 64              // 64 fp16 = 128B rows
#define STAGES 3
#define KITERS (KDIM / BK) // 8
#define NTHREADS 128

#define A_BYTES (BM * BK * 2)           // 16384
#define B_BYTES (BN * BK * 2)           // 16384
#define STAGE_BYTES (A_BYTES + B_BYTES) // 32768
#define SMEM_TOTAL (STAGES * STAGE_BYTES) // 98304  -> 2 CTAs/SM

// Scratch (static device globals: allocation-free per harness rules).
// fp16, "fragment-order" permuted k layout within each 32-k block:
//   k = 32*blk + 16h + 8u + 2t + e  ->  p = 32*blk + 8t + 4h + 2u + e
__device__ __align__(256) __half g_xh[BATCH * KDIM];
__device__ __align__(256) __half g_wph[NTOT * KDIM];

// ---------------------------------------------------------------------------
__device__ __forceinline__ int permh(int k) {
    return (k & ~31) | (((k >> 1) & 3) << 3) | (((k >> 4) & 1) << 2)
         | (((k >> 3) & 1) << 1) | (k & 1);
}

__device__ __forceinline__ uint32_t smem_u32(const void* p) {
    uint32_t a;
    asm("{ .reg .u64 t; cvta.to.shared.u64 t, %1; cvt.u32.u64 %0, t; }"
        : "=r"(a) : "l"(p));
    return a;
}

__device__ __forceinline__ void cp_async16(uint32_t dst, const void* src) {
    asm volatile("cp.async.cg.shared.global [%0], [%1], 16;"
                 :: "r"(dst), "l"(src) : "memory");
}
__device__ __forceinline__ void cp_commit() {
    asm volatile("cp.async.commit_group;" ::: "memory");
}
__device__ __forceinline__ void cp_wait1() {
    asm volatile("cp.async.wait_group 1;" ::: "memory");
}

__device__ __forceinline__ void lds128u(uint4& v, uint32_t addr) {
    asm volatile("ld.shared.v4.u32 {%0,%1,%2,%3}, [%4];"
                 : "=r"(v.x), "=r"(v.y), "=r"(v.z), "=r"(v.w)
                 : "r"(addr));
}

// m16n8k16 fp16 MMA, fp32 accumulate.
__device__ __forceinline__ void mma_f16(float* c,
                                        uint32_t a0, uint32_t a1,
                                        uint32_t a2, uint32_t a3,
                                        uint32_t b0, uint32_t b1) {
    asm volatile(
        "mma.sync.aligned.m16n8k16.row.col.f32.f16.f16.f32 "
        "{%0,%1,%2,%3}, {%4,%5,%6,%7}, {%8,%9}, {%0,%1,%2,%3};"
        : "+f"(c[0]), "+f"(c[1]), "+f"(c[2]), "+f"(c[3])
        : "r"(a0), "r"(a1), "r"(a2), "r"(a3), "r"(b0), "r"(b1));
}

// ---------------------------------------------------------------------------
// Setup 1: convert x to fp16, permuted layout (coalesced float4 reads).
// ---------------------------------------------------------------------------
__global__ void conv_x_kernel(const float4* __restrict__ x4) {
    int i = blockIdx.x * 256 + threadIdx.x;   // covers BATCH*KDIM/4 exactly
    float4 v = x4[i];
    int row = i >> 7;                         // 128 float4 per row
    int k = (i & 127) << 2;
    __half2* dst = reinterpret_cast<__half2*>(g_xh + (size_t)row * KDIM);
    dst[permh(k) >> 1]     = __floats2half2_rn(v.x, v.y);
    dst[permh(k + 2) >> 1] = __floats2half2_rn(v.z, v.w);
}

// ---------------------------------------------------------------------------
// Setup 2: per capsule c — G = W_c W_c^T + eps I (fp32), Cholesky G = R R^T,
// W'_c = R^{-1} W_c, stored fp16 permuted. One block per capsule.
// ---------------------------------------------------------------------------
__global__ __launch_bounds__(256) void prep_w_kernel(const float* __restrict__ w) {
    __shared__ float sW[8][516];
    __shared__ float sG[8][8];
    __shared__ float sR[8][8];
    __shared__ float sRinv[8];
    int c = blockIdx.x;
    int tid = threadIdx.x;

    for (int i = tid; i < 8 * 512; i += 256)
        sW[i >> 9][i & 511] = w[c * 4096 + i];
    __syncthreads();

    {   // gram: 4 threads per (d,e) pair, quad shuffle reduce
        int p = tid >> 2, sub = tid & 3;
        int d = p >> 3, e = p & 7;
        float s = 0.f;
        #pragma unroll 8
        for (int k = sub * 128; k < sub * 128 + 128; k++)
            s += sW[d][k] * sW[e][k];
        s += __shfl_xor_sync(0xffffffffu, s, 1);
        s += __shfl_xor_sync(0xffffffffu, s, 2);
        if (sub == 0) sG[d][e] = s + (d == e ? EPS_REG : 0.f);
    }
    __syncthreads();

    if (tid == 0) {
        float R[8][8];
        #pragma unroll
        for (int i = 0; i < 8; i++) {
            #pragma unroll
            for (int j = 0; j <= i; j++) {
                float s = sG[i][j];
                for (int k = 0; k < j; k++) s -= R[i][k] * R[j][k];
                if (i == j) R[i][i] = sqrtf(s);
                else        R[i][j] = s / R[j][j];
            }
        }
        #pragma unroll
        for (int i = 0; i < 8; i++) {
            sRinv[i] = 1.0f / R[i][i];
            #pragma unroll
            for (int j = 0; j <= i; j++) sR[i][j] = R[i][j];
        }
    }
    __syncthreads();

    for (int k = tid; k < 512; k += 256) {
        float y[8];
        #pragma unroll
        for (int d = 0; d < 8; d++) {
            float t = sW[d][k];
            #pragma unroll
            for (int j = 0; j < 8; j++)
                if (j < d) t -= sR[d][j] * y[j];
            y[d] = t * sRinv[d];
        }
        int pk = permh(k);
        #pragma unroll
        for (int d = 0; d < 8; d++)
            g_wph[(size_t)(c * 8 + d) * KDIM + pk] = __float2half_rn(y[d]);
    }
}

// ---------------------------------------------------------------------------
// Main GEMM: 128x128 tile per CTA, 128 threads (4 warps, 2m x 2n, 64x64 warp
// tiles). 3-stage cp.async ring (96KB) -> 2 CTAs/SM. Consumer is software-
// pipelined: per-stage A fragments batched up front; B fragments double-
// buffered so each 4-LDS group hides under the previous 32 MMAs.
// ---------------------------------------------------------------------------
__global__ __launch_bounds__(NTHREADS, 2) void caps_gemm_kernel(float* __restrict__ out) {
    extern __shared__ char smem[];
    const uint32_t sbase = smem_u32(smem);
    const int tid = threadIdx.x;
    const int lane = tid & 31;
    const int wid = tid >> 5;
    const int warp_m = wid & 1;       // 2 warps along M (64 rows each)
    const int warp_n = wid >> 1;      // 2 warps along N (64 cols each)
    const int g = lane >> 2;          // groupID
    const int tg = lane & 3;          // threadID_in_group
    const int m0 = blockIdx.y * BM;
    const int n0 = blockIdx.x * BN;

    // Producer: 16 x 16B chunks per thread per stage (8 A + 8 B).
    uint32_t dA[8], sA[8], dB[8], sB[8];
    #pragma unroll
    for (int i = 0; i < 8; i++) {
        int ch = i * NTHREADS + tid;          // 0..1023
        int row = ch >> 3, c = ch & 7;
        uint32_t sw = (uint32_t)((c ^ ((row & 1) << 2)) << 4);
        dA[i] = (uint32_t)(row * 128) + sw;
        sA[i] = (uint32_t)((m0 + row) * 1024 + c * 16);
        dB[i] = (uint32_t)(A_BYTES + row * 128) + sw;
        sB[i] = (uint32_t)((n0 + row) * 1024 + c * 16);
    }
    const char* xbase = (const char*)g_xh;
    const char* wbase = (const char*)g_wph;

    auto issue = [&](int kk, int s) {
        uint32_t st = sbase + (uint32_t)s * STAGE_BYTES;
        uint32_t ko = (uint32_t)kk * 128;
        #pragma unroll
        for (int i = 0; i < 8; i++)
            cp_async16(st + dA[i], xbase + sA[i] + ko);
        #pragma unroll
        for (int i = 0; i < 8; i++)
            cp_async16(st + dB[i], wbase + sB[i] + ko);
        cp_commit();
    };

    // Prologue: fill first 2 stages.
    issue(0, 0);
    issue(1, 1);

    float acc[4][8][4];
    #pragma unroll
    for (int mf = 0; mf < 4; mf++)
        #pragma unroll
        for (int nf = 0; nf < 8; nf++)
            #pragma unroll
            for (int r = 0; r < 4; r++) acc[mf][nf][r] = 0.f;

    // Consumer base offsets. All rows a thread touches share parity (g&1).
    const uint32_t aBase = (uint32_t)((warp_m * 64 + g) * 128);            // + mf*2048
    const uint32_t bBase = (uint32_t)(A_BYTES + (warp_n * 64 + g) * 128);  // + nf*1024
    const uint32_t par = (uint32_t)((g & 1) << 2);
    const uint32_t ckb0 = (uint32_t)((tg ^ par) << 4);        // block b=0
    const uint32_t ckb1 = (uint32_t)(((4 + tg) ^ par) << 4);  // block b=1

    int sCons = 0, sProd = 2;
    #pragma unroll 1
    for (int kk = 0; kk < KITERS; kk++) {
        cp_wait1();
        __syncthreads();
        if (kk + 2 < KITERS) {
            issue(kk + 2, sProd);
            if (++sProd == STAGES) sProd = 0;
        } else {
            cp_commit();   // empty group keeps wait_group accounting exact
        }

        uint32_t st = sbase + (uint32_t)sCons * STAGE_BYTES;
        if (++sCons == STAGES) sCons = 0;

        // ---- batch ALL A fragments for this stage (both 32-k blocks) ------
        uint4 AL[2][4], AH[2][4];
        #pragma unroll
        for (int mf = 0; mf < 4; mf++) {
            uint32_t a = st + aBase + (uint32_t)(mf * 2048);
            lds128u(AL[0][mf], a + ckb0);
            lds128u(AH[0][mf], a + 1024 + ckb0);
            lds128u(AL[1][mf], a + ckb1);
            lds128u(AH[1][mf], a + 1024 + ckb1);
        }

        // ---- B double-buffered over 4 groups (b, nfg) ---------------------
        uint4 Bb[2][4];
        #pragma unroll
        for (int q = 0; q < 4; q++)
            lds128u(Bb[0][q], st + bBase + (uint32_t)(q * 1024) + ckb0);

        #pragma unroll
        for (int grp = 0; grp < 4; grp++) {
            const int cur = grp & 1, nxt = cur ^ 1;
            if (grp < 3) {
                const int g2 = grp + 1;
                const int b2 = g2 >> 1, nf2 = g2 & 1;
                const uint32_t ck2 = b2 ? ckb1 : ckb0;
                #pragma unroll
                for (int q = 0; q < 4; q++)
                    lds128u(Bb[nxt][q],
                            st + bBase + (uint32_t)(nf2 * 4096 + q * 1024) + ck2);
            }
            const int b = grp >> 1, nfg = grp & 1;
            // h = 0 (words x,y)
            #pragma unroll
            for (int mf = 0; mf < 4; mf++) {
                #pragma unroll
                for (int q = 0; q < 4; q++) {
                    mma_f16(acc[mf][nfg * 4 + q],
                            AL[b][mf].x, AH[b][mf].x, AL[b][mf].y, AH[b][mf].y,
                            Bb[cur][q].x, Bb[cur][q].y);
                }
            }
            // h = 1 (words z,w)
            #pragma unroll
            for (int mf = 0; mf < 4; mf++) {
                #pragma unroll
                for (int q = 0; q < 4; q++) {
                    mma_f16(acc[mf][nfg * 4 + q],
                            AL[b][mf].z, AH[b][mf].z, AL[b][mf].w, AH[b][mf].w,
                            Bb[cur][q].z, Bb[cur][q].w);
                }
            }
        }
    }

    // ------------------- fused epilogue ------------------------------------
    // Each m16n8 accumulator frag covers one capsule. Quad butterfly over tg
    // sums the 8-col squares; tg==0 lanes store float4-vectorized results.
    const int capbase = (n0 >> 3) + warp_n * 8;
    #pragma unroll
    for (int mf = 0; mf < 4; mf++) {
        float r0[8], r1[8];
        #pragma unroll
        for (int nf = 0; nf < 8; nf++) {
            float* c = acc[mf][nf];
            float s0 = c[0] * c[0] + c[1] * c[1];
            float s1 = c[2] * c[2] + c[3] * c[3];
            s0 += __shfl_xor_sync(0xffffffffu, s0, 1);
            s0 += __shfl_xor_sync(0xffffffffu, s0, 2);
            s1 += __shfl_xor_sync(0xffffffffu, s1, 1);
            s1 += __shfl_xor_sync(0xffffffffu, s1, 2);
            r0[nf] = sqrtf(s0);
            r1[nf] = sqrtf(s1);
        }
        if (tg == 0) {
            int row = m0 + warp_m * 64 + mf * 16 + g;
            float* p0 = out + (size_t)row * NUM_CAPS + capbase;
            float* p1 = out + (size_t)(row + 8) * NUM_CAPS + capbase;
            *reinterpret_cast<float4*>(p0)     = make_float4(r0[0], r0[1], r0[2], r0[3]);
            *reinterpret_cast<float4*>(p0 + 4) = make_float4(r0[4], r0[5], r0[6], r0[7]);
            *reinterpret_cast<float4*>(p1)     = make_float4(r1[0], r1[1], r1[2], r1[3]);
            *reinterpret_cast<float4*>(p1 + 4) = make_float4(r1[4], r1[5], r1[6], r1[7]);
        }
    }
}

// ---------------------------------------------------------------------------
extern "C" void kernel_launch(void* const* d_in, const int* in_sizes, int n_in,
                              void* d_out, int out_size) {
    (void)in_sizes; (void)n_in; (void)out_size;
    const float* x = (const float*)d_in[0];
    // d_in[1] = eye (unused; eps*I applied analytically)
    const float* w = (const float*)d_in[2];
    float* out = (float*)d_out;

    conv_x_kernel<<<(BATCH * KDIM / 4) / 256, 256>>>(
        reinterpret_cast<const float4*>(x));
    prep_w_kernel<<<NUM_CAPS, 256>>>(w);

    cudaFuncSetAttribute(caps_gemm_kernel,
                         cudaFuncAttributeMaxDynamicSharedMemorySize, SMEM_TOTAL);
    caps_gemm_kernel<<<dim3(NTOT / BN, BATCH / BM), NTHREADS, SMEM_TOTAL>>>(out);
}

// round 11
// speedup vs baseline: 1.0296x; 1.0296x over previous
#include <cuda_runtime.h>
#include <cuda_fp16.h>
#include <cstdint>

// ============================================================================
// LinearCapsPro:  out[b,c] = sqrt( u_c^T (W_c W_c^T + eps I)^{-1} u_c ),
//                 u_c = W_c x_b
// Restructured:   G_c = R_c R_c^T (Cholesky)  =>  out[b,c] = || (R_c^{-1} W_c) x_b ||
// Prep W' = R^{-1} W (tiny), then ONE fp16 GEMM y = x @ W'^T with a fused
// sum-of-squares + sqrt epilogue (y never touches memory).
//
// R6-R10 evidence: GEMM pinned at ~257us across all organizations -> legacy
// HMMA issue floor (~4cyc/MMA/SM); ceiling ~239us. R11 harvests overheads:
// persistent 296-CTA (2/SM) continuous cp.async ring (kills per-wave fill),
// coalesced-store conv_x, smem-staged coalesced prep_w stores.
// ============================================================================

#define BATCH 8192
#define KDIM 512
#define NTOT 8192          // C*D
#define NUM_CAPS 1024
#define EPS_REG 1e-4f

#define BM 128
#define BN 128
#define BK 64              // 64 fp16 = 128B rows
#define STAGES 3
#define KPT 8              // k-iters per tile
#define GRIDX 296          // persistent CTAs, 2 per SM
#define NTILES 4096        // (8192/128) * (8192/128)
#define NTHREADS 128

#define A_BYTES (BM * BK * 2)           // 16384
#define B_BYTES (BN * BK * 2)           // 16384
#define STAGE_BYTES (A_BYTES + B_BYTES) // 32768
#define SMEM_TOTAL (STAGES * STAGE_BYTES) // 98304 -> 2 CTAs/SM

// Scratch (static device globals: allocation-free per harness rules).
// fp16, "fragment-order" permuted k layout within each 32-k block:
//   k = 32*blk + 16h + 8u + 2t + e  ->  p = 32*blk + 8t + 4h + 2u + e
__device__ __align__(256) __half g_xh[BATCH * KDIM];
__device__ __align__(256) __half g_wph[NTOT * KDIM];

// ---------------------------------------------------------------------------
__device__ __forceinline__ int permh(int k) {
    return (k & ~31) | (((k >> 1) & 3) << 3) | (((k >> 4) & 1) << 2)
         | (((k >> 3) & 1) << 1) | (k & 1);
}

__device__ __forceinline__ uint32_t smem_u32(const void* p) {
    uint32_t a;
    asm("{ .reg .u64 t; cvta.to.shared.u64 t, %1; cvt.u32.u64 %0, t; }"
        : "=r"(a) : "l"(p));
    return a;
}

__device__ __forceinline__ void cp_async16(uint32_t dst, const void* src) {
    asm volatile("cp.async.cg.shared.global [%0], [%1], 16;"
                 :: "r"(dst), "l"(src) : "memory");
}
__device__ __forceinline__ void cp_commit() {
    asm volatile("cp.async.commit_group;" ::: "memory");
}
__device__ __forceinline__ void cp_wait1() {
    asm volatile("cp.async.wait_group 1;" ::: "memory");
}

__device__ __forceinline__ void lds128u(uint4& v, uint32_t addr) {
    asm volatile("ld.shared.v4.u32 {%0,%1,%2,%3}, [%4];"
                 : "=r"(v.x), "=r"(v.y), "=r"(v.z), "=r"(v.w)
                 : "r"(addr));
}

// m16n8k16 fp16 MMA, fp32 accumulate.
__device__ __forceinline__ void mma_f16(float* c,
                                        uint32_t a0, uint32_t a1,
                                        uint32_t a2, uint32_t a3,
                                        uint32_t b0, uint32_t b1) {
    asm volatile(
        "mma.sync.aligned.m16n8k16.row.col.f32.f16.f16.f32 "
        "{%0,%1,%2,%3}, {%4,%5,%6,%7}, {%8,%9}, {%0,%1,%2,%3};"
        : "+f"(c[0]), "+f"(c[1]), "+f"(c[2]), "+f"(c[3])
        : "r"(a0), "r"(a1), "r"(a2), "r"(a3), "r"(b0), "r"(b1));
}

__device__ __forceinline__ uint32_t h2u(float a, float b) {
    __half2 h = __floats2half2_rn(a, b);
    return *reinterpret_cast<uint32_t*>(&h);
}

// ---------------------------------------------------------------------------
// Setup 1: convert x to fp16 permuted. Inverted mapping: each thread OWNS one
// contiguous 16B dest chunk (coalesced uint4 store) and gathers the 4 float2
// source pairs it needs. Dest chunk (blk,t) holds p=8t+4h+2u+e -> k=16h+8u+2t+e.
// ---------------------------------------------------------------------------
__global__ void conv_x_kernel(const float2* __restrict__ x2) {
    int i = blockIdx.x * 256 + threadIdx.x;   // chunk id; covers 524288 exactly
    int row = i >> 6;                         // 64 chunks per row
    int c = i & 63;
    int blk = c >> 2, t = c & 3;
    const float2* src = x2 + (size_t)row * 256 + blk * 16 + t;  // k/2 = 16blk+8h+4u+t
    float2 v00 = src[0];   // h=0,u=0
    float2 v01 = src[4];   // h=0,u=1
    float2 v10 = src[8];   // h=1,u=0
    float2 v11 = src[12];  // h=1,u=1
    uint4 o;
    o.x = h2u(v00.x, v00.y);   // word 0: p=8t+0,1   (h=0,u=0)
    o.y = h2u(v01.x, v01.y);   // word 1: p=8t+2,3   (h=0,u=1)
    o.z = h2u(v10.x, v10.y);   // word 2: p=8t+4,5   (h=1,u=0)
    o.w = h2u(v11.x, v11.y);   // word 3: p=8t+6,7   (h=1,u=1)
    reinterpret_cast<uint4*>(g_xh)[i] = o;
}

// ---------------------------------------------------------------------------
// Setup 2: per capsule c — G = W_c W_c^T + eps I (fp32), Cholesky G = R R^T,
// W'_c = R^{-1} W_c. Results staged permuted in smem (fp16), then written out
// as contiguous 16B chunks (coalesced). One block per capsule.
// ---------------------------------------------------------------------------
__global__ __launch_bounds__(256) void prep_w_kernel(const float* __restrict__ w) {
    __shared__ float sW[8][516];
    __shared__ float sG[8][8];
    __shared__ float sR[8][8];
    __shared__ float sRinv[8];
    __shared__ __half sY[8][512];
    int c = blockIdx.x;
    int tid = threadIdx.x;

    for (int i = tid; i < 8 * 512; i += 256)
        sW[i >> 9][i & 511] = w[c * 4096 + i];
    __syncthreads();

    {   // gram: 4 threads per (d,e) pair, quad shuffle reduce
        int p = tid >> 2, sub = tid & 3;
        int d = p >> 3, e = p & 7;
        float s = 0.f;
        #pragma unroll 8
        for (int k = sub * 128; k < sub * 128 + 128; k++)
            s += sW[d][k] * sW[e][k];
        s += __shfl_xor_sync(0xffffffffu, s, 1);
        s += __shfl_xor_sync(0xffffffffu, s, 2);
        if (sub == 0) sG[d][e] = s + (d == e ? EPS_REG : 0.f);
    }
    __syncthreads();

    if (tid == 0) {
        float R[8][8];
        #pragma unroll
        for (int i = 0; i < 8; i++) {
            #pragma unroll
            for (int j = 0; j <= i; j++) {
                float s = sG[i][j];
                for (int k = 0; k < j; k++) s -= R[i][k] * R[j][k];
                if (i == j) R[i][i] = sqrtf(s);
                else        R[i][j] = s / R[j][j];
            }
        }
        #pragma unroll
        for (int i = 0; i < 8; i++) {
            sRinv[i] = 1.0f / R[i][i];
            #pragma unroll
            for (int j = 0; j <= i; j++) sR[i][j] = R[i][j];
        }
    }
    __syncthreads();

    for (int k = tid; k < 512; k += 256) {
        float y[8];
        #pragma unroll
        for (int d = 0; d < 8; d++) {
            float t = sW[d][k];
            #pragma unroll
            for (int j = 0; j < 8; j++)
                if (j < d) t -= sR[d][j] * y[j];
            y[d] = t * sRinv[d];
        }
        int pk = permh(k);
        #pragma unroll
        for (int d = 0; d < 8; d++)
            sY[d][pk] = __float2half_rn(y[d]);
    }
    __syncthreads();

    // Coalesced output: sY already holds the permuted layout; plain 16B copy.
    for (int i = tid; i < 512; i += 256) {
        int d = i >> 6, ch = i & 63;
        reinterpret_cast<uint4*>(g_wph + (size_t)(c * 8 + d) * KDIM)[ch] =
            reinterpret_cast<const uint4*>(sY[d])[ch];
    }
}

// ---------------------------------------------------------------------------
// Persistent GEMM: 296 CTAs (2/SM), each owns tiles t = bid + w*296 (128x128).
// ONE continuous 3-stage cp.async ring across all of a CTA's tiles (global
// iter gi = w*8 + kk): fill paid once per CTA, epilogue overlaps next tile's
// loads, and the co-resident CTA covers sync bubbles. Inner loop = R9 (best).
// ---------------------------------------------------------------------------
__global__ __launch_bounds__(NTHREADS, 2) void caps_gemm_kernel(float* __restrict__ out) {
    extern __shared__ char smem[];
    const uint32_t sbase = smem_u32(smem);
    const int tid = threadIdx.x;
    const int lane = tid & 31;
    const int wid = tid >> 5;
    const int warp_m = wid & 1;       // 2 warps along M (64 rows each)
    const int warp_n = wid >> 1;      // 2 warps along N (64 cols each)
    const int g = lane >> 2;          // groupID
    const int tg = lane & 3;          // threadID_in_group
    const int bid = blockIdx.x;

    const int myTiles = (NTILES - bid + GRIDX - 1) / GRIDX;  // 13 or 14
    const int totalIters = myTiles * KPT;

    // Producer: 16 x 16B chunks per thread per stage (8 A + 8 B).
    // Fixed smem dest offsets + tile-relative source offsets.
    uint32_t dA[8], rsrc[8], dB[8];
    #pragma unroll
    for (int i = 0; i < 8; i++) {
        int ch = i * NTHREADS + tid;          // 0..1023
        int row = ch >> 3, c = ch & 7;
        uint32_t sw = (uint32_t)((c ^ ((row & 1) << 2)) << 4);
        dA[i] = (uint32_t)(row * 128) + sw;
        dB[i] = (uint32_t)(A_BYTES + row * 128) + sw;
        rsrc[i] = (uint32_t)(row * 1024 + c * 16);
    }
    const char* xbase = (const char*)g_xh;
    const char* wbase = (const char*)g_wph;

    auto issue = [&](int gi, int s) {
        int t = bid + (gi >> 3) * GRIDX;
        uint32_t ko = (uint32_t)((gi & 7) * 128);
        uint32_t xoff = (uint32_t)((t >> 6) << 7) * 1024 + ko;   // m0*1024
        uint32_t woff = (uint32_t)((t & 63) << 7) * 1024 + ko;   // n0*1024
        uint32_t st = sbase + (uint32_t)s * STAGE_BYTES;
        #pragma unroll
        for (int i = 0; i < 8; i++)
            cp_async16(st + dA[i], xbase + (xoff + rsrc[i]));
        #pragma unroll
        for (int i = 0; i < 8; i++)
            cp_async16(st + dB[i], wbase + (woff + rsrc[i]));
        cp_commit();
    };

    // Prologue: fill first 2 stages (totalIters >= 104 always).
    issue(0, 0);
    issue(1, 1);

    float acc[4][8][4];
    #pragma unroll
    for (int mf = 0; mf < 4; mf++)
        #pragma unroll
        for (int nf = 0; nf < 8; nf++)
            #pragma unroll
            for (int r = 0; r < 4; r++) acc[mf][nf][r] = 0.f;

    // Consumer base offsets. All rows a thread touches share parity (g&1).
    uint32_t aRow[4], bRow[8];
    #pragma unroll
    for (int mf = 0; mf < 4; mf++) aRow[mf] = (warp_m * 64 + mf * 16 + g) * 128;
    #pragma unroll
    for (int nf = 0; nf < 8; nf++) bRow[nf] = A_BYTES + (warp_n * 64 + nf * 8 + g) * 128;
    const uint32_t par = (uint32_t)((g & 1) << 2);

    int sCons = 0, sProd = 2;
    #pragma unroll 1
    for (int gi = 0; gi < totalIters; gi++) {
        cp_wait1();
        __syncthreads();
        if (gi + 2 < totalIters) {
            issue(gi + 2, sProd);
            if (++sProd == STAGES) sProd = 0;
        } else {
            cp_commit();   // empty group keeps wait_group accounting exact
        }

        uint32_t st = sbase + (uint32_t)sCons * STAGE_BYTES;
        if (++sCons == STAGES) sCons = 0;
        #pragma unroll
        for (int b = 0; b < 2; b++) {          // two 32-k blocks per stage
            uint32_t ck = (uint32_t)(((4 * b + tg) ^ par) << 4);
            uint4 aLo[4], aHi[4];
            #pragma unroll
            for (int mf = 0; mf < 4; mf++) {
                lds128u(aLo[mf], st + aRow[mf] + ck);
                lds128u(aHi[mf], st + aRow[mf] + 1024 + ck);  // +8 rows
            }
            #pragma unroll
            for (int nfg = 0; nfg < 2; nfg++) {
                uint4 bF[4];
                #pragma unroll
                for (int q = 0; q < 4; q++)
                    lds128u(bF[q], st + bRow[nfg * 4 + q] + ck);
                #pragma unroll
                for (int mf = 0; mf < 4; mf++) {
                    #pragma unroll
                    for (int q = 0; q < 4; q++) {
                        mma_f16(acc[mf][nfg * 4 + q],
                                aLo[mf].x, aHi[mf].x, aLo[mf].y, aHi[mf].y,
                                bF[q].x, bF[q].y);
                    }
                }
                #pragma unroll
                for (int mf = 0; mf < 4; mf++) {
                    #pragma unroll
                    for (int q = 0; q < 4; q++) {
                        mma_f16(acc[mf][nfg * 4 + q],
                                aLo[mf].z, aHi[mf].z, aLo[mf].w, aHi[mf].w,
                                bF[q].z, bF[q].w);
                    }
                }
            }
        }

        if ((gi & 7) == 7) {
            // ------------- fused epilogue for the tile just finished -------
            int t = bid + (gi >> 3) * GRIDX;
            int m0 = (t >> 6) << 7;
            int n0 = (t & 63) << 7;
            const int capbase = (n0 >> 3) + warp_n * 8;
            #pragma unroll
            for (int mf = 0; mf < 4; mf++) {
                float r0[8], r1[8];
                #pragma unroll
                for (int nf = 0; nf < 8; nf++) {
                    float* c = acc[mf][nf];
                    float s0 = c[0] * c[0] + c[1] * c[1];
                    float s1 = c[2] * c[2] + c[3] * c[3];
                    s0 += __shfl_xor_sync(0xffffffffu, s0, 1);
                    s0 += __shfl_xor_sync(0xffffffffu, s0, 2);
                    s1 += __shfl_xor_sync(0xffffffffu, s1, 1);
                    s1 += __shfl_xor_sync(0xffffffffu, s1, 2);
                    r0[nf] = sqrtf(s0);
                    r1[nf] = sqrtf(s1);
                }
                if (tg == 0) {
                    int row = m0 + warp_m * 64 + mf * 16 + g;
                    float* p0 = out + (size_t)row * NUM_CAPS + capbase;
                    float* p1 = out + (size_t)(row + 8) * NUM_CAPS + capbase;
                    *reinterpret_cast<float4*>(p0)     = make_float4(r0[0], r0[1], r0[2], r0[3]);
                    *reinterpret_cast<float4*>(p0 + 4) = make_float4(r0[4], r0[5], r0[6], r0[7]);
                    *reinterpret_cast<float4*>(p1)     = make_float4(r1[0], r1[1], r1[2], r1[3]);
                    *reinterpret_cast<float4*>(p1 + 4) = make_float4(r1[4], r1[5], r1[6], r1[7]);
                }
            }
            #pragma unroll
            for (int mf = 0; mf < 4; mf++)
                #pragma unroll
                for (int nf = 0; nf < 8; nf++)
                    #pragma unroll
                    for (int r = 0; r < 4; r++) acc[mf][nf][r] = 0.f;
        }
    }
}

// ---------------------------------------------------------------------------
extern "C" void kernel_launch(void* const* d_in, const int* in_sizes, int n_in,
                              void* d_out, int out_size) {
    (void)in_sizes; (void)n_in; (void)out_size;
    const float* x = (const float*)d_in[0];
    // d_in[1] = eye (unused; eps*I applied analytically)
    const float* w = (const float*)d_in[2];
    float* out = (float*)d_out;

    conv_x_kernel<<<2048, 256>>>(reinterpret_cast<const float2*>(x));
    prep_w_kernel<<<NUM_CAPS, 256>>>(w);

    cudaFuncSetAttribute(caps_gemm_kernel,
                         cudaFuncAttributeMaxDynamicSharedMemorySize, SMEM_TOTAL);
    caps_gemm_kernel<<<GRIDX, NTHREADS, SMEM_TOTAL>>>(out);
}

// round 14
// speedup vs baseline: 1.1329x; 1.1003x over previous
#include <cuda_runtime.h>
#include <cuda_fp16.h>
#include <cstdint>

// ============================================================================
// LinearCapsPro:  out[b,c] = sqrt( u_c^T (W_c W_c^T + eps I)^{-1} u_c ),
//                 u_c = W_c x_b
// Restructured:   G_c = R_c R_c^T (Cholesky)  =>  out[b,c] = || (R_c^{-1} W_c) x_b ||
// Prep W' = R^{-1} W (tiny), then ONE fp16 GEMM y = x @ W'^T with a fused
// sum-of-squares + sqrt epilogue (y never touches memory).
//
// R7/R8/R10/R11 all regressed vs R9's GEMM (128x128, 4 warps, 64x64 warp
// tiles, 3-stage ring, 2 CTAs/SM). R12 = R9 GEMM verbatim + faster preps:
// coalesced-store conv_x, smem-staged + float4-load prep_w.
// ============================================================================

#define BATCH 8192
#define KDIM 512
#define NTOT 8192          // C*D
#define NUM_CAPS 1024
#define EPS_REG 1e-4f

#define BM 128
#define BN 128
#define BK 64              // 64 fp16 = 128B rows
#define STAGES 3
#define KITERS (KDIM / BK) // 8
#define NTHREADS 128

#define A_BYTES (BM * BK * 2)           // 16384
#define B_BYTES (BN * BK * 2)           // 16384
#define STAGE_BYTES (A_BYTES + B_BYTES) // 32768
#define SMEM_TOTAL (STAGES * STAGE_BYTES) // 98304  -> 2 CTAs/SM

// Scratch (static device globals: allocation-free per harness rules).
// fp16, "fragment-order" permuted k layout within each 32-k block:
//   k = 32*blk + 16h + 8u + 2t + e  ->  p = 32*blk + 8t + 4h + 2u + e
__device__ __align__(256) __half g_xh[BATCH * KDIM];
__device__ __align__(256) __half g_wph[NTOT * KDIM];

// ---------------------------------------------------------------------------
__device__ __forceinline__ int permh(int k) {
    return (k & ~31) | (((k >> 1) & 3) << 3) | (((k >> 4) & 1) << 2)
         | (((k >> 3) & 1) << 1) | (k & 1);
}

__device__ __forceinline__ uint32_t smem_u32(const void* p) {
    uint32_t a;
    asm("{ .reg .u64 t; cvta.to.shared.u64 t, %1; cvt.u32.u64 %0, t; }"
        : "=r"(a) : "l"(p));
    return a;
}

__device__ __forceinline__ void cp_async16(uint32_t dst, const void* src) {
    asm volatile("cp.async.cg.shared.global [%0], [%1], 16;"
                 :: "r"(dst), "l"(src) : "memory");
}
__device__ __forceinline__ void cp_commit() {
    asm volatile("cp.async.commit_group;" ::: "memory");
}
__device__ __forceinline__ void cp_wait1() {
    asm volatile("cp.async.wait_group 1;" ::: "memory");
}

__device__ __forceinline__ void lds128u(uint4& v, uint32_t addr) {
    asm volatile("ld.shared.v4.u32 {%0,%1,%2,%3}, [%4];"
                 : "=r"(v.x), "=r"(v.y), "=r"(v.z), "=r"(v.w)
                 : "r"(addr));
}

// m16n8k16 fp16 MMA, fp32 accumulate.
__device__ __forceinline__ void mma_f16(float* c,
                                        uint32_t a0, uint32_t a1,
                                        uint32_t a2, uint32_t a3,
                                        uint32_t b0, uint32_t b1) {
    asm volatile(
        "mma.sync.aligned.m16n8k16.row.col.f32.f16.f16.f32 "
        "{%0,%1,%2,%3}, {%4,%5,%6,%7}, {%8,%9}, {%0,%1,%2,%3};"
        : "+f"(c[0]), "+f"(c[1]), "+f"(c[2]), "+f"(c[3])
        : "r"(a0), "r"(a1), "r"(a2), "r"(a3), "r"(b0), "r"(b1));
}

__device__ __forceinline__ uint32_t h2u(float a, float b) {
    __half2 h = __floats2half2_rn(a, b);
    return *reinterpret_cast<uint32_t*>(&h);
}

// ---------------------------------------------------------------------------
// Setup 1: convert x to fp16 permuted. Each thread OWNS one contiguous 16B
// dest chunk (coalesced uint4 store) and gathers its 4 float2 source pairs.
// Dest chunk (blk,t) holds p=8t+4h+2u+e -> k=16h+8u+2t+e.
// ---------------------------------------------------------------------------
__global__ void conv_x_kernel(const float2* __restrict__ x2) {
    int i = blockIdx.x * 256 + threadIdx.x;   // chunk id; covers 524288 exactly
    int row = i >> 6;                         // 64 chunks per row
    int c = i & 63;
    int blk = c >> 2, t = c & 3;
    const float2* src = x2 + (size_t)row * 256 + blk * 16 + t;  // k/2 = 16blk+8h+4u+t
    float2 v00 = src[0];   // h=0,u=0
    float2 v01 = src[4];   // h=0,u=1
    float2 v10 = src[8];   // h=1,u=0
    float2 v11 = src[12];  // h=1,u=1
    uint4 o;
    o.x = h2u(v00.x, v00.y);
    o.y = h2u(v01.x, v01.y);
    o.z = h2u(v10.x, v10.y);
    o.w = h2u(v11.x, v11.y);
    reinterpret_cast<uint4*>(g_xh)[i] = o;
}

// ---------------------------------------------------------------------------
// Setup 2: per capsule c — G = W_c W_c^T + eps I (fp32), Cholesky G = R R^T,
// W'_c = R^{-1} W_c. float4 gmem loads; results staged permuted in smem
// (fp16) then written as contiguous 16B chunks. One block per capsule.
// ---------------------------------------------------------------------------
__global__ __launch_bounds__(256) void prep_w_kernel(const float4* __restrict__ w4) {
    __shared__ float sW[8][516];
    __shared__ float sG[8][8];
    __shared__ float sR[8][8];
    __shared__ float sRinv[8];
    __shared__ __half sY[8][512];
    int c = blockIdx.x;
    int tid = threadIdx.x;

    // 1024 float4 per capsule; 4 per thread, coalesced.
    #pragma unroll
    for (int j = 0; j < 4; j++) {
        int i = j * 256 + tid;                // float4 index 0..1023
        float4 v = w4[(size_t)c * 1024 + i];
        int d = i >> 7, k = (i & 127) << 2;   // 128 float4 per row
        sW[d][k] = v.x; sW[d][k + 1] = v.y; sW[d][k + 2] = v.z; sW[d][k + 3] = v.w;
    }
    __syncthreads();

    {   // gram: 4 threads per (d,e) pair, quad shuffle reduce
        int p = tid >> 2, sub = tid & 3;
        int d = p >> 3, e = p & 7;
        float s = 0.f;
        #pragma unroll 8
        for (int k = sub * 128; k < sub * 128 + 128; k++)
            s += sW[d][k] * sW[e][k];
        s += __shfl_xor_sync(0xffffffffu, s, 1);
        s += __shfl_xor_sync(0xffffffffu, s, 2);
        if (sub == 0) sG[d][e] = s + (d == e ? EPS_REG : 0.f);
    }
    __syncthreads();

    if (tid == 0) {
        float R[8][8];
        #pragma unroll
        for (int i = 0; i < 8; i++) {
            #pragma unroll
            for (int j = 0; j <= i; j++) {
                float s = sG[i][j];
                for (int k = 0; k < j; k++) s -= R[i][k] * R[j][k];
                if (i == j) R[i][i] = sqrtf(s);
                else        R[i][j] = s / R[j][j];
            }
        }
        #pragma unroll
        for (int i = 0; i < 8; i++) {
            sRinv[i] = 1.0f / R[i][i];
            #pragma unroll
            for (int j = 0; j <= i; j++) sR[i][j] = R[i][j];
        }
    }
    __syncthreads();

    for (int k = tid; k < 512; k += 256) {
        float y[8];
        #pragma unroll
        for (int d = 0; d < 8; d++) {
            float t = sW[d][k];
            #pragma unroll
            for (int j = 0; j < 8; j++)
                if (j < d) t -= sR[d][j] * y[j];
            y[d] = t * sRinv[d];
        }
        int pk = permh(k);
        #pragma unroll
        for (int d = 0; d < 8; d++)
            sY[d][pk] = __float2half_rn(y[d]);
    }
    __syncthreads();

    // Coalesced output: sY already holds the permuted layout; plain 16B copy.
    for (int i = tid; i < 512; i += 256) {
        int d = i >> 6, ch = i & 63;
        reinterpret_cast<uint4*>(g_wph + (size_t)(c * 8 + d) * KDIM)[ch] =
            reinterpret_cast<const uint4*>(sY[d])[ch];
    }
}

// ---------------------------------------------------------------------------
// Main GEMM (R9 verbatim — best measured): 128x128 tile per CTA, 128 threads
// (4 warps, 2m x 2n, 64x64 warp tiles). 3-stage cp.async ring (96KB) ->
// 2 CTAs/SM. Fused epilogue: out[b,cap] = sqrt(sum_{d<8} y^2), float4 stores.
// ---------------------------------------------------------------------------
__global__ __launch_bounds__(NTHREADS, 2) void caps_gemm_kernel(float* __restrict__ out) {
    extern __shared__ char smem[];
    const uint32_t sbase = smem_u32(smem);
    const int tid = threadIdx.x;
    const int lane = tid & 31;
    const int wid = tid >> 5;
    const int warp_m = wid & 1;       // 2 warps along M (64 rows each)
    const int warp_n = wid >> 1;      // 2 warps along N (64 cols each)
    const int g = lane >> 2;          // groupID
    const int tg = lane & 3;          // threadID_in_group
    const int m0 = blockIdx.y * BM;
    const int n0 = blockIdx.x * BN;

    // Producer: 16 x 16B chunks per thread per stage (8 A + 8 B).
    uint32_t dA[8], sA[8], dB[8], sB[8];
    #pragma unroll
    for (int i = 0; i < 8; i++) {
        int ch = i * NTHREADS + tid;          // 0..1023
        int row = ch >> 3, c = ch & 7;
        uint32_t sw = (uint32_t)((c ^ ((row & 1) << 2)) << 4);
        dA[i] = (uint32_t)(row * 128) + sw;
        sA[i] = (uint32_t)((m0 + row) * 1024 + c * 16);
        dB[i] = (uint32_t)(A_BYTES + row * 128) + sw;
        sB[i] = (uint32_t)((n0 + row) * 1024 + c * 16);
    }
    const char* xbase = (const char*)g_xh;
    const char* wbase = (const char*)g_wph;

    auto issue = [&](int kk, int s) {
        uint32_t st = sbase + (uint32_t)s * STAGE_BYTES;
        uint32_t ko = (uint32_t)kk * 128;
        #pragma unroll
        for (int i = 0; i < 8; i++)
            cp_async16(st + dA[i], xbase + sA[i] + ko);
        #pragma unroll
        for (int i = 0; i < 8; i++)
            cp_async16(st + dB[i], wbase + sB[i] + ko);
        cp_commit();
    };

    // Prologue: fill first 2 stages.
    issue(0, 0);
    issue(1, 1);

    float acc[4][8][4];
    #pragma unroll
    for (int mf = 0; mf < 4; mf++)
        #pragma unroll
        for (int nf = 0; nf < 8; nf++)
            #pragma unroll
            for (int r = 0; r < 4; r++) acc[mf][nf][r] = 0.f;

    // Consumer base offsets. All rows a thread touches share parity (g&1).
    uint32_t aRow[4], bRow[8];
    #pragma unroll
    for (int mf = 0; mf < 4; mf++) aRow[mf] = (warp_m * 64 + mf * 16 + g) * 128;
    #pragma unroll
    for (int nf = 0; nf < 8; nf++) bRow[nf] = A_BYTES + (warp_n * 64 + nf * 8 + g) * 128;
    const uint32_t par = (uint32_t)((g & 1) << 2);

    int sCons = 0, sProd = 2;
    #pragma unroll 1
    for (int kk = 0; kk < KITERS; kk++) {
        cp_wait1();
        __syncthreads();
        if (kk + 2 < KITERS) {
            issue(kk + 2, sProd);
            if (++sProd == STAGES) sProd = 0;
        } else {
            cp_commit();   // empty group keeps wait_group accounting exact
        }

        uint32_t st = sbase + (uint32_t)sCons * STAGE_BYTES;
        if (++sCons == STAGES) sCons = 0;
        #pragma unroll
        for (int b = 0; b < 2; b++) {          // two 32-k blocks per stage
            uint32_t ck = (uint32_t)(((4 * b + tg) ^ par) << 4);
            uint4 aLo[4], aHi[4];
            #pragma unroll
            for (int mf = 0; mf < 4; mf++) {
                lds128u(aLo[mf], st + aRow[mf] + ck);
                lds128u(aHi[mf], st + aRow[mf] + 1024 + ck);  // +8 rows
            }
            #pragma unroll
            for (int nfg = 0; nfg < 2; nfg++) {
                uint4 bF[4];
                #pragma unroll
                for (int q = 0; q < 4; q++)
                    lds128u(bF[q], st + bRow[nfg * 4 + q] + ck);
                #pragma unroll
                for (int mf = 0; mf < 4; mf++) {
                    #pragma unroll
                    for (int q = 0; q < 4; q++) {
                        mma_f16(acc[mf][nfg * 4 + q],
                                aLo[mf].x, aHi[mf].x, aLo[mf].y, aHi[mf].y,
                                bF[q].x, bF[q].y);
                    }
                }
                #pragma unroll
                for (int mf = 0; mf < 4; mf++) {
                    #pragma unroll
                    for (int q = 0; q < 4; q++) {
                        mma_f16(acc[mf][nfg * 4 + q],
                                aLo[mf].z, aHi[mf].z, aLo[mf].w, aHi[mf].w,
                                bF[q].z, bF[q].w);
                    }
                }
            }
        }
    }

    // ------------------- fused epilogue ------------------------------------
    // Each m16n8 accumulator frag covers one capsule. Quad butterfly over tg
    // sums the 8-col squares; tg==0 lanes store float4-vectorized results.
    const int capbase = (n0 >> 3) + warp_n * 8;
    #pragma unroll
    for (int mf = 0; mf < 4; mf++) {
        float r0[8], r1[8];
        #pragma unroll
        for (int nf = 0; nf < 8; nf++) {
            float* c = acc[mf][nf];
            float s0 = c[0] * c[0] + c[1] * c[1];
            float s1 = c[2] * c[2] + c[3] * c[3];
            s0 += __shfl_xor_sync(0xffffffffu, s0, 1);
            s0 += __shfl_xor_sync(0xffffffffu, s0, 2);
            s1 += __shfl_xor_sync(0xffffffffu, s1, 1);
            s1 += __shfl_xor_sync(0xffffffffu, s1, 2);
            r0[nf] = sqrtf(s0);
            r1[nf] = sqrtf(s1);
        }
        if (tg == 0) {
            int row = m0 + warp_m * 64 + mf * 16 + g;
            float* p0 = out + (size_t)row * NUM_CAPS + capbase;
            float* p1 = out + (size_t)(row + 8) * NUM_CAPS + capbase;
            *reinterpret_cast<float4*>(p0)     = make_float4(r0[0], r0[1], r0[2], r0[3]);
            *reinterpret_cast<float4*>(p0 + 4) = make_float4(r0[4], r0[5], r0[6], r0[7]);
            *reinterpret_cast<float4*>(p1)     = make_float4(r1[0], r1[1], r1[2], r1[3]);
            *reinterpret_cast<float4*>(p1 + 4) = make_float4(r1[4], r1[5], r1[6], r1[7]);
        }
    }
}

// ---------------------------------------------------------------------------
extern "C" void kernel_launch(void* const* d_in, const int* in_sizes, int n_in,
                              void* d_out, int out_size) {
    (void)in_sizes; (void)n_in; (void)out_size;
    const float* x = (const float*)d_in[0];
    // d_in[1] = eye (unused; eps*I applied analytically)
    const float* w = (const float*)d_in[2];
    float* out = (float*)d_out;

    conv_x_kernel<<<2048, 256>>>(reinterpret_cast<const float2*>(x));
    prep_w_kernel<<<NUM_CAPS, 256>>>(reinterpret_cast<const float4*>(w));

    cudaFuncSetAttribute(caps_gemm_kernel,
                         cudaFuncAttributeMaxDynamicSharedMemorySize, SMEM_TOTAL);
    caps_gemm_kernel<<<dim3(NTOT / BN, BATCH / BM), NTHREADS, SMEM_TOTAL>>>(out);
}